// round 3
// baseline (speedup 1.0000x reference)
#include <cuda_runtime.h>
#include <cstdint>

// Problem constants
#define BATCH 512
#define CHANNELS 256
#define KX 6            // template size
#define KZ 22           // search size
#define HO 17           // output size (22-6+1)
#define OUT_PER_B (HO*HO)           // 289
#define N_OUT (BATCH*OUT_PER_B)     // 147968

// Tiling
#define SPLITS 4                    // channel splits per batch
#define CH_PER_SPLIT (CHANNELS/SPLITS)   // 64
#define CH_CHUNK 16                 // channels staged per iteration
#define ITERS (CH_PER_SPLIT/CH_CHUNK)    // 4
#define THREADS 272                 // 17 rows x 16 channel lanes

// smem z layout: row padded 22 -> 28 floats (112B, 16B aligned)
#define ZROW_PAD 28
#define ZCH_FLOATS (KZ*ZROW_PAD)    // 616 floats per channel

// Partial results: [split][batch][289]
__device__ float g_partial[SPLITS * N_OUT];

__global__ __launch_bounds__(THREADS, 3)
void corr_main_kernel(const float* __restrict__ x, const float* __restrict__ z)
{
    __shared__ float z_s[CH_CHUNK * ZCH_FLOATS];   // 16*616*4 = 39424 B
    __shared__ float x_s[CH_CHUNK * KX * KX];      // 16*36*4  =  2304 B

    const int tid = threadIdx.x;
    const int i   = tid % HO;     // output row this thread owns (0..16)
    const int cl  = tid / HO;     // channel lane (0..15)

    const int b     = blockIdx.x >> 2;
    const int split = blockIdx.x & 3;
    const int cbase = split * CH_PER_SPLIT;

    float acc[HO];
    #pragma unroll
    for (int j = 0; j < HO; j++) acc[j] = 0.f;

    for (int it = 0; it < ITERS; ++it) {
        const int c0 = cbase + it * CH_CHUNK;
        __syncthreads();  // previous chunk's compute done before restaging

        // ---- stage z: 16 contiguous channels = 7744 floats = 1936 float4 ----
        {
            const float4* zsrc = reinterpret_cast<const float4*>(
                z + ((size_t)b * CHANNELS + c0) * (KZ * KZ));
            for (int u = tid; u < (CH_CHUNK * KZ * KZ) / 4; u += THREADS) {
                float4 v = zsrc[u];
                int e = u * 4;                 // element idx within 16-ch slab
                int c_local = e / (KZ * KZ);   // 484 floats/channel, 484%4==0
                int w = e - c_local * (KZ * KZ);
                int r = w / KZ;
                int col = w - r * KZ;
                float vals[4] = {v.x, v.y, v.z, v.w};
                #pragma unroll
                for (int q = 0; q < 4; q++) {
                    int rr = r, cc = col + q;
                    if (cc >= KZ) { cc -= KZ; rr++; }
                    z_s[c_local * ZCH_FLOATS + rr * ZROW_PAD + cc] = vals[q];
                }
            }
        }
        // ---- stage x: 16 channels * 36 floats = 144 float4 ----
        {
            const float4* xsrc = reinterpret_cast<const float4*>(
                x + ((size_t)b * CHANNELS + c0) * (KX * KX));
            float4* xs4 = reinterpret_cast<float4*>(x_s);
            for (int u = tid; u < (CH_CHUNK * KX * KX) / 4; u += THREADS)
                xs4[u] = xsrc[u];
        }
        __syncthreads();

        // ---- compute: channel c0+cl, output row i ----
        const float* zc = &z_s[cl * ZCH_FLOATS];
        const float* xc = &x_s[cl * (KX * KX)];
        #pragma unroll
        for (int ky = 0; ky < KX; ky++) {
            float zr[24];
            const float4* zr4 =
                reinterpret_cast<const float4*>(zc + (i + ky) * ZROW_PAD);
            #pragma unroll
            for (int q = 0; q < 6; q++) {
                float4 t = zr4[q];
                zr[4*q+0] = t.x; zr[4*q+1] = t.y;
                zr[4*q+2] = t.z; zr[4*q+3] = t.w;
            }
            #pragma unroll
            for (int kx = 0; kx < KX; kx++) {
                const float xv = xc[ky * KX + kx];
                #pragma unroll
                for (int j = 0; j < HO; j++)
                    acc[j] = fmaf(zr[j + kx], xv, acc[j]);
            }
        }
    }

    // ---- reduce over the 16 channel lanes (reuse z_s as scratch) ----
    __syncthreads();
    #pragma unroll
    for (int j = 0; j < HO; j++)
        z_s[cl * OUT_PER_B + i * HO + j] = acc[j];
    __syncthreads();

    // 289 outputs, 272 threads -> strided loop (threads 0..16 take a 2nd one).
    for (int o = tid; o < OUT_PER_B; o += THREADS) {
        float s = 0.f;
        #pragma unroll
        for (int c2 = 0; c2 < CH_CHUNK; c2++)
            s += z_s[c2 * OUT_PER_B + o];
        g_partial[((size_t)split * BATCH + b) * OUT_PER_B + o] = s;
    }
}

__global__ void corr_reduce_kernel(float* __restrict__ out)
{
    int idx = blockIdx.x * blockDim.x + threadIdx.x;
    if (idx < N_OUT) {
        out[idx] = g_partial[idx]
                 + g_partial[N_OUT + idx]
                 + g_partial[2 * N_OUT + idx]
                 + g_partial[3 * N_OUT + idx];
    }
}

extern "C" void kernel_launch(void* const* d_in, const int* in_sizes, int n_in,
                              void* d_out, int out_size)
{
    const float* a = (const float*)d_in[0];
    const float* bptr = (const float*)d_in[1];
    // x has 512*256*36 = 4718592 elems; z has 512*256*484 = 63438848
    const float* x;
    const float* z;
    if (in_sizes[0] == BATCH * CHANNELS * KX * KX) { x = a;    z = bptr; }
    else                                           { x = bptr; z = a;   }

    float* out = (float*)d_out;

    corr_main_kernel<<<BATCH * SPLITS, THREADS>>>(x, z);
    corr_reduce_kernel<<<(N_OUT + 255) / 256, 256>>>(out);
}

// round 4
// speedup vs baseline: 1.1303x; 1.1303x over previous
#include <cuda_runtime.h>
#include <cstdint>

#define BATCH 512
#define CHANNELS 256
#define KXS 6            // template size
#define KZ 22            // search size
#define HO 17            // output size
#define OUT_PER_B 289
#define N_OUT (BATCH*OUT_PER_B)

#define SPLITS 4
#define CH_PER_SPLIT 64
#define CH_CHUNK 16
#define ITERS 4
#define THREADS 272      // 17 rows x 16 channel lanes

#define ZROW_PAD 28
#define ZCH_FLOATS (KZ*ZROW_PAD)            // 616
#define Z_SMEM_FLOATS (CH_CHUNK*ZCH_FLOATS) // 9856
#define ZCHUNK_F4 ((CH_CHUNK*KZ*KZ)/4)      // 1936
#define XCHUNK_F4 ((CH_CHUNK*KXS*KXS)/4)    // 144
#define PF 8             // prefetch float4 per thread (1936 = 7*272 + 32)

typedef unsigned long long ull;

__device__ float g_partial[SPLITS * N_OUT];

__device__ __forceinline__ ull pack2(float lo, float hi) {
    ull r; asm("mov.b64 %0, {%1, %2};" : "=l"(r) : "f"(lo), "f"(hi)); return r;
}
__device__ __forceinline__ void unpack2(ull v, float& lo, float& hi) {
    asm("mov.b64 {%0, %1}, %2;" : "=f"(lo), "=f"(hi) : "l"(v));
}
__device__ __forceinline__ void fma2(ull& d, ull a, ull b) {
    asm("fma.rn.f32x2 %0, %1, %2, %0;" : "+l"(d) : "l"(a), "l"(b));
}

__global__ __launch_bounds__(THREADS, 2)
void corr_main_kernel(const float* __restrict__ x, const float* __restrict__ z)
{
    __shared__ float z_s[Z_SMEM_FLOATS];           // 39424 B
    __shared__ float x_s[CH_CHUNK * KXS * KXS];    //  2304 B

    const int tid = threadIdx.x;
    const int i   = tid % HO;     // output row owned by this thread
    const int cl  = tid / HO;     // channel lane 0..15

    const int b     = blockIdx.x >> 2;
    const int split = blockIdx.x & 3;
    const int cbase = split * CH_PER_SPLIT;

    // ---- precompute chunk-invariant de-swizzle mapping for my PF float4s ----
    // soff[k]: bits[0:23] float offset into z_s, bit 24 = straddle, -1 = invalid
    int soff[PF];
    #pragma unroll
    for (int k = 0; k < PF; k++) {
        int u = tid + k * THREADS;
        if (u < ZCHUNK_F4) {
            int e = u * 4;                    // element within 16-ch slab
            int c_local = e / (KZ * KZ);      // 484 floats/channel
            int w = e - c_local * (KZ * KZ);
            int r = w / KZ;
            int col = w - r * KZ;             // col is even, <= 20
            int base = c_local * ZCH_FLOATS + r * ZROW_PAD + col;
            int straddle = (col == 20) ? 1 : 0;   // last 2 elems go to next row
            soff[k] = base | (straddle << 24);
        } else {
            soff[k] = -1;
        }
    }

    const float4* zsrc = reinterpret_cast<const float4*>(
        z + ((size_t)b * CHANNELS + cbase) * (KZ * KZ));
    const float4* xsrc = reinterpret_cast<const float4*>(
        x + ((size_t)b * CHANNELS + cbase) * (KXS * KXS));

    // ---- zero z_s once (pads stay zero; staging never writes them) ----
    {
        float4* zs4 = reinterpret_cast<float4*>(z_s);
        for (int u = tid; u < Z_SMEM_FLOATS / 4; u += THREADS)
            zs4[u] = make_float4(0.f, 0.f, 0.f, 0.f);
    }

    // ---- prefetch chunk 0 into registers ----
    float4 v[PF];
    float4 xv4;
    {
        const float4* p = zsrc;   // chunk 0
        #pragma unroll
        for (int k = 0; k < PF; k++) {
            int u = tid + k * THREADS;
            if (u < ZCHUNK_F4) v[k] = p[u];
        }
        if (tid < XCHUNK_F4) xv4 = xsrc[tid];
    }
    __syncthreads();   // zeroing done before stores

    // ---- store chunk 0 ----
    #pragma unroll
    for (int k = 0; k < PF; k++) {
        int s = soff[k];
        if (s >= 0) {
            int base = s & 0xFFFFFF;
            int bump = (s >> 24) ? 6 : 0;
            z_s[base + 0]        = v[k].x;
            z_s[base + 1]        = v[k].y;
            z_s[base + 2 + bump] = v[k].z;
            z_s[base + 3 + bump] = v[k].w;
        }
    }
    if (tid < XCHUNK_F4) reinterpret_cast<float4*>(x_s)[tid] = xv4;
    __syncthreads();

    // ---- accumulators: 17 outputs as 9 packed f32x2 (slot 17 is dummy) ----
    ull a[9];
    #pragma unroll
    for (int j = 0; j < 9; j++) a[j] = 0ull;

    for (int it = 0; it < ITERS; ++it) {
        // prefetch next chunk (LDG latency overlaps compute below)
        if (it < ITERS - 1) {
            const float4* p = zsrc + (size_t)(it + 1) * ZCHUNK_F4;
            #pragma unroll
            for (int k = 0; k < PF; k++) {
                int u = tid + k * THREADS;
                if (u < ZCHUNK_F4) v[k] = p[u];
            }
            if (tid < XCHUNK_F4) xv4 = xsrc[(it + 1) * XCHUNK_F4 + tid];
        }

        // ---- compute: channel cl of this chunk, output row i ----
        const float* zc = &z_s[cl * ZCH_FLOATS];
        const float* xc = &x_s[cl * (KXS * KXS)];
        #pragma unroll
        for (int ky = 0; ky < KXS; ky++) {
            float zr[24];
            const float4* zr4 =
                reinterpret_cast<const float4*>(zc + (i + ky) * ZROW_PAD);
            #pragma unroll
            for (int q = 0; q < 6; q++) {
                float4 t = zr4[q];
                zr[4*q+0] = t.x; zr[4*q+1] = t.y;
                zr[4*q+2] = t.z; zr[4*q+3] = t.w;
            }
            // aligned and shifted packed views of the row
            ull za[11], zb[11];
            #pragma unroll
            for (int k = 0; k < 11; k++) {
                za[k] = pack2(zr[2*k],     zr[2*k+1]);
                zb[k] = pack2(zr[2*k + 1], zr[2*k + 2]);
            }
            #pragma unroll
            for (int kx = 0; kx < KXS; kx++) {
                float xv = xc[ky * KXS + kx];
                ull xx = pack2(xv, xv);
                if (kx & 1) {
                    const int o = kx >> 1;          // (kx-1)/2
                    #pragma unroll
                    for (int j2 = 0; j2 < 9; j2++) fma2(a[j2], zb[j2 + o], xx);
                } else {
                    const int o = kx >> 1;
                    #pragma unroll
                    for (int j2 = 0; j2 < 9; j2++) fma2(a[j2], za[j2 + o], xx);
                }
            }
        }

        // swap in next chunk
        if (it < ITERS - 1) {
            __syncthreads();   // all threads done reading current chunk
            #pragma unroll
            for (int k = 0; k < PF; k++) {
                int s = soff[k];
                if (s >= 0) {
                    int base = s & 0xFFFFFF;
                    int bump = (s >> 24) ? 6 : 0;
                    z_s[base + 0]        = v[k].x;
                    z_s[base + 1]        = v[k].y;
                    z_s[base + 2 + bump] = v[k].z;
                    z_s[base + 3 + bump] = v[k].w;
                }
            }
            if (tid < XCHUNK_F4) reinterpret_cast<float4*>(x_s)[tid] = xv4;
            __syncthreads();
        }
    }

    // ---- reduce over the 16 channel lanes (reuse z_s as scratch) ----
    __syncthreads();
    #pragma unroll
    for (int j2 = 0; j2 < 9; j2++) {
        float lo, hi;
        unpack2(a[j2], lo, hi);
        z_s[cl * OUT_PER_B + i * HO + 2*j2] = lo;
        if (2*j2 + 1 < HO)
            z_s[cl * OUT_PER_B + i * HO + 2*j2 + 1] = hi;
    }
    __syncthreads();

    for (int o = tid; o < OUT_PER_B; o += THREADS) {
        float s = 0.f;
        #pragma unroll
        for (int c2 = 0; c2 < CH_CHUNK; c2++)
            s += z_s[c2 * OUT_PER_B + o];
        g_partial[((size_t)split * BATCH + b) * OUT_PER_B + o] = s;
    }
}

__global__ void corr_reduce_kernel(float* __restrict__ out)
{
    int idx = blockIdx.x * blockDim.x + threadIdx.x;
    if (idx < N_OUT) {
        out[idx] = g_partial[idx]
                 + g_partial[N_OUT + idx]
                 + g_partial[2 * N_OUT + idx]
                 + g_partial[3 * N_OUT + idx];
    }
}

extern "C" void kernel_launch(void* const* d_in, const int* in_sizes, int n_in,
                              void* d_out, int out_size)
{
    const float* a = (const float*)d_in[0];
    const float* bptr = (const float*)d_in[1];
    const float* x;
    const float* z;
    if (in_sizes[0] == BATCH * CHANNELS * KXS * KXS) { x = a;    z = bptr; }
    else                                             { x = bptr; z = a;   }

    float* out = (float*)d_out;

    corr_main_kernel<<<BATCH * SPLITS, THREADS>>>(x, z);
    corr_reduce_kernel<<<(N_OUT + 255) / 256, 256>>>(out);
}